// round 1
// baseline (speedup 1.0000x reference)
#include <cuda_runtime.h>
#include <math.h>

// ============================================================================
// Actor_att1 fused kernel — one thread per batch row, packed f32x2 math.
//
// Per row (obs_dim = 127):
//   self_out = relu(relu(x[0:4] @ en_w1 + en_b1) @ en_w2 + en_b2)       (16)
//   other:  15 entities, in5 = [pos(2), vel(2), scal(1)]
//           enc = relu(relu(in5 @ oa_w1 + b1) @ oa_w2 + b2)             (16)
//           attn-softmax(self_out . enc / 4) -> weighted sum -> LN -> relu
//   food:   16 entities, in3 -> same with g_* weights
//   merged = [self_out, food_out, other_out]  (48)
//   h1 = lrelu(merged @ m_w1 + b1); h2 = lrelu(h1 @ m_w2 + b2)
//   out = tanh(h2 @ m_w3 + b3)                                          (2)
// ============================================================================

typedef unsigned long long u64;
#define DINL __device__ __forceinline__

DINL u64 f2pack(float lo, float hi) {
    u64 d; asm("mov.b64 %0, {%1, %2};" : "=l"(d) : "f"(lo), "f"(hi)); return d;
}
DINL u64 f2splat(float v) {
    u64 d; asm("mov.b64 %0, {%1, %1};" : "=l"(d) : "f"(v)); return d;
}
DINL void f2unpack(u64 v, float& lo, float& hi) {
    asm("mov.b64 {%0, %1}, %2;" : "=f"(lo), "=f"(hi) : "l"(v));
}
DINL u64 f2fma(u64 a, u64 b, u64 c) {
    u64 d; asm("fma.rn.f32x2 %0, %1, %2, %3;" : "=l"(d) : "l"(a), "l"(b), "l"(c)); return d;
}
DINL u64 f2mul(u64 a, u64 b) {
    u64 d; asm("mul.rn.f32x2 %0, %1, %2;" : "=l"(d) : "l"(a), "l"(b)); return d;
}

// Dense layer: acc(2*NP outs, packed) = b + sum_k in[k] * w[k][:]
// w is row-major (K, 2*NP). All loops fully unrolled (register arrays).
template<int K, int NP>
DINL void dense_packed(const float* in, const float* __restrict__ w,
                       const float* __restrict__ b, u64* acc) {
    const u64* bp = reinterpret_cast<const u64*>(b);
#pragma unroll
    for (int p = 0; p < NP; p++) acc[p] = bp[p];
#pragma unroll
    for (int k = 0; k < K; k++) {
        u64 xs = f2splat(in[k]);
        const u64* wr = reinterpret_cast<const u64*>(w) + k * NP;
#pragma unroll
        for (int p = 0; p < NP; p++) acc[p] = f2fma(xs, wr[p], acc[p]);
    }
}

template<int NP>
DINL void relu_unpack(const u64* acc, float* out) {
#pragma unroll
    for (int p = 0; p < NP; p++) {
        float a, b; f2unpack(acc[p], a, b);
        out[2 * p]     = fmaxf(a, 0.f);
        out[2 * p + 1] = fmaxf(b, 0.f);
    }
}

template<int NP>
DINL void leaky_unpack(const u64* acc, float* out) {
#pragma unroll
    for (int p = 0; p < NP; p++) {
        float a, b; f2unpack(acc[p], a, b);
        out[2 * p]     = fmaxf(a, 0.01f * a);   // leaky_relu(0.01): works for both signs
        out[2 * p + 1] = fmaxf(b, 0.01f * b);
    }
}

// Shared weight storage. Every member size is a multiple of 16 floats (64B)
// so every array is 16B aligned for vector LDS.
struct SW {
    float en_w1[4 * 32];  float en_b1[32];  float en_w2[32 * 16]; float en_b2[16];
    float oa_w1[5 * 32];  float oa_b1[32];  float oa_w2[32 * 16]; float oa_b2[16];
    float oa_g[16];       float oa_bln[16];
    float g_w1[3 * 32];   float g_b1[32];   float g_w2[32 * 16];  float g_b2[16];
    float g_g[16];        float g_bln[16];
    float m_w1[48 * 32];  float m_b1[32];   float m_w2[32 * 32];  float m_b2[32];
    float m_w3[32 * 2];   float m_b3[16];   // m_b3 padded (only 2 used)
};

DINL void cp_smem(float* dst, const float* __restrict__ src, int n, int tid, int nt) {
    for (int i = tid; i < n; i += nt) dst[i] = src[i];
}

__global__ void __launch_bounds__(256)
actor_kernel(const float* __restrict__ s_in,
             const float* __restrict__ en_w1, const float* __restrict__ en_b1,
             const float* __restrict__ en_w2, const float* __restrict__ en_b2,
             const float* __restrict__ oa_w1, const float* __restrict__ oa_b1,
             const float* __restrict__ oa_w2, const float* __restrict__ oa_b2,
             const float* __restrict__ oa_g,  const float* __restrict__ oa_bln,
             const float* __restrict__ g_w1,  const float* __restrict__ g_b1,
             const float* __restrict__ g_w2,  const float* __restrict__ g_b2,
             const float* __restrict__ g_g,   const float* __restrict__ g_bln,
             const float* __restrict__ m_w1,  const float* __restrict__ m_b1,
             const float* __restrict__ m_w2,  const float* __restrict__ m_b2,
             const float* __restrict__ m_w3,  const float* __restrict__ m_b3,
             float* __restrict__ out, int B)
{
    __shared__ __align__(16) SW sw;
    const int tid = threadIdx.x, nt = blockDim.x;

    cp_smem(sw.en_w1, en_w1, 4 * 32, tid, nt);
    cp_smem(sw.en_b1, en_b1, 32, tid, nt);
    cp_smem(sw.en_w2, en_w2, 32 * 16, tid, nt);
    cp_smem(sw.en_b2, en_b2, 16, tid, nt);
    cp_smem(sw.oa_w1, oa_w1, 5 * 32, tid, nt);
    cp_smem(sw.oa_b1, oa_b1, 32, tid, nt);
    cp_smem(sw.oa_w2, oa_w2, 32 * 16, tid, nt);
    cp_smem(sw.oa_b2, oa_b2, 16, tid, nt);
    cp_smem(sw.oa_g, oa_g, 16, tid, nt);
    cp_smem(sw.oa_bln, oa_bln, 16, tid, nt);
    cp_smem(sw.g_w1, g_w1, 3 * 32, tid, nt);
    cp_smem(sw.g_b1, g_b1, 32, tid, nt);
    cp_smem(sw.g_w2, g_w2, 32 * 16, tid, nt);
    cp_smem(sw.g_b2, g_b2, 16, tid, nt);
    cp_smem(sw.g_g, g_g, 16, tid, nt);
    cp_smem(sw.g_bln, g_bln, 16, tid, nt);
    cp_smem(sw.m_w1, m_w1, 48 * 32, tid, nt);
    cp_smem(sw.m_b1, m_b1, 32, tid, nt);
    cp_smem(sw.m_w2, m_w2, 32 * 32, tid, nt);
    cp_smem(sw.m_b2, m_b2, 32, tid, nt);
    cp_smem(sw.m_w3, m_w3, 32 * 2, tid, nt);
    if (tid < 2) sw.m_b3[tid] = m_b3[tid];
    __syncthreads();

    const int r = blockIdx.x * blockDim.x + tid;
    if (r >= B) return;

    const float* __restrict__ x = s_in + (size_t)r * 127;

    // ---------------- self encoder: 4 -> 32 -> 16 ----------------
    float self_out[16];
    {
        float in4[4];
#pragma unroll
        for (int k = 0; k < 4; k++) in4[k] = x[k];
        u64 a1[16];
        dense_packed<4, 16>(in4, sw.en_w1, sw.en_b1, a1);
        float h[32];
        relu_unpack<16>(a1, h);
        u64 a2[8];
        dense_packed<32, 8>(h, sw.en_w2, sw.en_b2, a2);
        relu_unpack<8>(a2, self_out);
    }

    // packed self_out for fast dot products
    u64 sp[8];
#pragma unroll
    for (int p = 0; p < 8; p++) sp[p] = f2pack(self_out[2 * p], self_out[2 * p + 1]);

    // ---------------- other-agent attention (15 entities, 5-d in) ----------------
    float other_out[16];
    {
        float mmax = -__int_as_float(0x7f800000);  // -inf
        float l = 0.f;
        u64 att[8];
#pragma unroll
        for (int p = 0; p < 8; p++) att[p] = 0ull;

#pragma unroll 1
        for (int i = 0; i < 15; i++) {
            float in5[5];
            in5[0] = x[4 + 2 * i];
            in5[1] = x[5 + 2 * i];
            in5[2] = x[34 + 2 * i];
            in5[3] = x[35 + 2 * i];
            in5[4] = x[64 + i];

            u64 a1[16];
            dense_packed<5, 16>(in5, sw.oa_w1, sw.oa_b1, a1);
            float h[32];
            relu_unpack<16>(a1, h);
            u64 a2[8];
            dense_packed<32, 8>(h, sw.oa_w2, sw.oa_b2, a2);
            float ef[16];
            relu_unpack<8>(a2, ef);
            u64 e[8];
#pragma unroll
            for (int p = 0; p < 8; p++) e[p] = f2pack(ef[2 * p], ef[2 * p + 1]);

            // score = (self_out . enc) / sqrt(16)
            u64 d2 = f2mul(sp[0], e[0]);
#pragma unroll
            for (int p = 1; p < 8; p++) d2 = f2fma(sp[p], e[p], d2);
            float dl, dh; f2unpack(d2, dl, dh);
            float s = (dl + dh) * 0.25f;

            // online softmax update
            float nm = fmaxf(mmax, s);
            float corr = __expf(mmax - nm);
            float pw   = __expf(s - nm);
            mmax = nm;
            l = l * corr + pw;
            u64 c2 = f2splat(corr), p2 = f2splat(pw);
#pragma unroll
            for (int p = 0; p < 8; p++) att[p] = f2fma(c2, att[p], f2mul(p2, e[p]));
        }

        float inv = __fdividef(1.f, l);
        float a16[16];
#pragma unroll
        for (int p = 0; p < 8; p++) {
            float a, b; f2unpack(att[p], a, b);
            a16[2 * p] = a * inv; a16[2 * p + 1] = b * inv;
        }
        // layernorm + relu
        float mu = 0.f;
#pragma unroll
        for (int d = 0; d < 16; d++) mu += a16[d];
        mu *= (1.f / 16.f);
        float var = 0.f;
#pragma unroll
        for (int d = 0; d < 16; d++) { float c = a16[d] - mu; var += c * c; }
        var *= (1.f / 16.f);
        float rs = rsqrtf(var + 1e-5f);
#pragma unroll
        for (int d = 0; d < 16; d++)
            other_out[d] = fmaxf((a16[d] - mu) * rs * sw.oa_g[d] + sw.oa_bln[d], 0.f);
    }

    // ---------------- food attention (16 entities, 3-d in) ----------------
    float food_out[16];
    {
        float mmax = -__int_as_float(0x7f800000);
        float l = 0.f;
        u64 att[8];
#pragma unroll
        for (int p = 0; p < 8; p++) att[p] = 0ull;

#pragma unroll 1
        for (int i = 0; i < 16; i++) {
            float in3[3];
            in3[0] = x[79 + 3 * i];
            in3[1] = x[80 + 3 * i];
            in3[2] = x[81 + 3 * i];

            u64 a1[16];
            dense_packed<3, 16>(in3, sw.g_w1, sw.g_b1, a1);
            float h[32];
            relu_unpack<16>(a1, h);
            u64 a2[8];
            dense_packed<32, 8>(h, sw.g_w2, sw.g_b2, a2);
            float ef[16];
            relu_unpack<8>(a2, ef);
            u64 e[8];
#pragma unroll
            for (int p = 0; p < 8; p++) e[p] = f2pack(ef[2 * p], ef[2 * p + 1]);

            u64 d2 = f2mul(sp[0], e[0]);
#pragma unroll
            for (int p = 1; p < 8; p++) d2 = f2fma(sp[p], e[p], d2);
            float dl, dh; f2unpack(d2, dl, dh);
            float s = (dl + dh) * 0.25f;

            float nm = fmaxf(mmax, s);
            float corr = __expf(mmax - nm);
            float pw   = __expf(s - nm);
            mmax = nm;
            l = l * corr + pw;
            u64 c2 = f2splat(corr), p2 = f2splat(pw);
#pragma unroll
            for (int p = 0; p < 8; p++) att[p] = f2fma(c2, att[p], f2mul(p2, e[p]));
        }

        float inv = __fdividef(1.f, l);
        float a16[16];
#pragma unroll
        for (int p = 0; p < 8; p++) {
            float a, b; f2unpack(att[p], a, b);
            a16[2 * p] = a * inv; a16[2 * p + 1] = b * inv;
        }
        float mu = 0.f;
#pragma unroll
        for (int d = 0; d < 16; d++) mu += a16[d];
        mu *= (1.f / 16.f);
        float var = 0.f;
#pragma unroll
        for (int d = 0; d < 16; d++) { float c = a16[d] - mu; var += c * c; }
        var *= (1.f / 16.f);
        float rs = rsqrtf(var + 1e-5f);
#pragma unroll
        for (int d = 0; d < 16; d++)
            food_out[d] = fmaxf((a16[d] - mu) * rs * sw.g_g[d] + sw.g_bln[d], 0.f);
    }

    // ---------------- merge head: 48 -> 32 -> 32 -> 2 ----------------
    float mg[48];
#pragma unroll
    for (int d = 0; d < 16; d++) {
        mg[d] = self_out[d];
        mg[16 + d] = food_out[d];
        mg[32 + d] = other_out[d];
    }

    u64 acc1[16];
    dense_packed<48, 16>(mg, sw.m_w1, sw.m_b1, acc1);
    float h1[32];
    leaky_unpack<16>(acc1, h1);

    u64 acc2[16];
    dense_packed<32, 16>(h1, sw.m_w2, sw.m_b2, acc2);
    float h2[32];
    leaky_unpack<16>(acc2, h2);

    u64 acc3[1];
    dense_packed<32, 1>(h2, sw.m_w3, sw.m_b3, acc3);
    float o0, o1; f2unpack(acc3[0], o0, o1);
    o0 = tanhf(o0);
    o1 = tanhf(o1);

    reinterpret_cast<float2*>(out)[r] = make_float2(o0, o1);
}

extern "C" void kernel_launch(void* const* d_in, const int* in_sizes, int n_in,
                              void* d_out, int out_size) {
    const float* s_in = (const float*)d_in[0];
    const int B = in_sizes[0] / 127;
    dim3 grid((B + 255) / 256), block(256);
    actor_kernel<<<grid, block>>>(
        s_in,
        (const float*)d_in[1],  (const float*)d_in[2],
        (const float*)d_in[3],  (const float*)d_in[4],
        (const float*)d_in[5],  (const float*)d_in[6],
        (const float*)d_in[7],  (const float*)d_in[8],
        (const float*)d_in[9],  (const float*)d_in[10],
        (const float*)d_in[11], (const float*)d_in[12],
        (const float*)d_in[13], (const float*)d_in[14],
        (const float*)d_in[15], (const float*)d_in[16],
        (const float*)d_in[17], (const float*)d_in[18],
        (const float*)d_in[19], (const float*)d_in[20],
        (const float*)d_in[21], (const float*)d_in[22],
        (float*)d_out, B);
}

// round 2
// speedup vs baseline: 2.3116x; 2.3116x over previous
#include <cuda_runtime.h>
#include <math.h>

// ============================================================================
// Actor_att1 fused kernel — one thread per batch row, packed f32x2 math.
// R2: coalesced smem input staging + no register spills (128thr/255reg).
// ============================================================================

typedef unsigned long long u64;
#define DINL __device__ __forceinline__

DINL u64 f2pack(float lo, float hi) {
    u64 d; asm("mov.b64 %0, {%1, %2};" : "=l"(d) : "f"(lo), "f"(hi)); return d;
}
DINL u64 f2splat(float v) {
    u64 d; asm("mov.b64 %0, {%1, %1};" : "=l"(d) : "f"(v)); return d;
}
DINL void f2unpack(u64 v, float& lo, float& hi) {
    asm("mov.b64 {%0, %1}, %2;" : "=f"(lo), "=f"(hi) : "l"(v));
}
DINL u64 f2fma(u64 a, u64 b, u64 c) {
    u64 d; asm("fma.rn.f32x2 %0, %1, %2, %3;" : "=l"(d) : "l"(a), "l"(b), "l"(c)); return d;
}
DINL u64 f2mul(u64 a, u64 b) {
    u64 d; asm("mul.rn.f32x2 %0, %1, %2;" : "=l"(d) : "l"(a), "l"(b)); return d;
}

// Dense layer: acc (2*NP outputs, packed) = b + sum_k in[k] * w[k][:]
// w row-major (K, 2*NP) in shared memory. 16B LDS for weight pairs.
template<int K, int NP>
DINL void dense_packed(const float* in, const float* __restrict__ w,
                       const float* __restrict__ b, u64* acc) {
    if constexpr (NP % 2 == 0) {
        const ulonglong2* bp = reinterpret_cast<const ulonglong2*>(b);
#pragma unroll
        for (int p = 0; p < NP / 2; p++) {
            ulonglong2 t = bp[p];
            acc[2 * p] = t.x; acc[2 * p + 1] = t.y;
        }
#pragma unroll
        for (int k = 0; k < K; k++) {
            u64 xs = f2splat(in[k]);
            const ulonglong2* wr = reinterpret_cast<const ulonglong2*>(w + k * 2 * NP);
#pragma unroll
            for (int p = 0; p < NP / 2; p++) {
                ulonglong2 t = wr[p];
                acc[2 * p]     = f2fma(xs, t.x, acc[2 * p]);
                acc[2 * p + 1] = f2fma(xs, t.y, acc[2 * p + 1]);
            }
        }
    } else {
        const u64* bp = reinterpret_cast<const u64*>(b);
#pragma unroll
        for (int p = 0; p < NP; p++) acc[p] = bp[p];
#pragma unroll
        for (int k = 0; k < K; k++) {
            u64 xs = f2splat(in[k]);
            const u64* wr = reinterpret_cast<const u64*>(w) + k * NP;
#pragma unroll
            for (int p = 0; p < NP; p++) acc[p] = f2fma(xs, wr[p], acc[p]);
        }
    }
}

template<int NP>
DINL void relu_unpack(const u64* acc, float* out) {
#pragma unroll
    for (int p = 0; p < NP; p++) {
        float a, b; f2unpack(acc[p], a, b);
        out[2 * p]     = fmaxf(a, 0.f);
        out[2 * p + 1] = fmaxf(b, 0.f);
    }
}

template<int NP>
DINL void leaky_unpack(const u64* acc, float* out) {
#pragma unroll
    for (int p = 0; p < NP; p++) {
        float a, b; f2unpack(acc[p], a, b);
        out[2 * p]     = fmaxf(a, 0.01f * a);
        out[2 * p + 1] = fmaxf(b, 0.01f * b);
    }
}

// Weights in shared memory; every array 16B aligned.
struct SW {
    float en_w1[4 * 32];  float en_b1[32];  float en_w2[32 * 16]; float en_b2[16];
    float oa_w1[5 * 32];  float oa_b1[32];  float oa_w2[32 * 16]; float oa_b2[16];
    float oa_g[16];       float oa_bln[16];
    float g_w1[3 * 32];   float g_b1[32];   float g_w2[32 * 16];  float g_b2[16];
    float g_g[16];        float g_bln[16];
    float m_w1[48 * 32];  float m_b1[32];   float m_w2[32 * 32];  float m_b2[32];
    float m_w3[32 * 2];   float m_b3[16];
};

DINL void cp_smem(float* dst, const float* __restrict__ src, int n, int tid, int nt) {
    for (int i = tid; i < n; i += nt) dst[i] = src[i];
}

#define NT 128
#define OBS 127

__global__ void __launch_bounds__(NT)
actor_kernel(const float* __restrict__ s_in,
             const float* __restrict__ en_w1, const float* __restrict__ en_b1,
             const float* __restrict__ en_w2, const float* __restrict__ en_b2,
             const float* __restrict__ oa_w1, const float* __restrict__ oa_b1,
             const float* __restrict__ oa_w2, const float* __restrict__ oa_b2,
             const float* __restrict__ oa_g,  const float* __restrict__ oa_bln,
             const float* __restrict__ g_w1,  const float* __restrict__ g_b1,
             const float* __restrict__ g_w2,  const float* __restrict__ g_b2,
             const float* __restrict__ g_g,   const float* __restrict__ g_bln,
             const float* __restrict__ m_w1,  const float* __restrict__ m_b1,
             const float* __restrict__ m_w2,  const float* __restrict__ m_b2,
             const float* __restrict__ m_w3,  const float* __restrict__ m_b3,
             float* __restrict__ out, int B)
{
    extern __shared__ __align__(16) float smem[];
    float* xs = smem;                               // NT * OBS floats
    SW* sw = reinterpret_cast<SW*>(smem + NT * OBS);

    const int tid = threadIdx.x;

    // ---- coalesced input staging: NT rows = NT*OBS contiguous floats ----
    {
        const size_t base = (size_t)blockIdx.x * NT * OBS;
        const float4* src4 = reinterpret_cast<const float4*>(s_in + base);
        float4* dst4 = reinterpret_cast<float4*>(xs);
        const int n4 = NT * OBS / 4;                // 4064, exact
#pragma unroll 4
        for (int i = tid; i < n4; i += NT) dst4[i] = src4[i];
    }

    // ---- stage weights ----
    cp_smem(sw->en_w1, en_w1, 4 * 32, tid, NT);
    cp_smem(sw->en_b1, en_b1, 32, tid, NT);
    cp_smem(sw->en_w2, en_w2, 32 * 16, tid, NT);
    cp_smem(sw->en_b2, en_b2, 16, tid, NT);
    cp_smem(sw->oa_w1, oa_w1, 5 * 32, tid, NT);
    cp_smem(sw->oa_b1, oa_b1, 32, tid, NT);
    cp_smem(sw->oa_w2, oa_w2, 32 * 16, tid, NT);
    cp_smem(sw->oa_b2, oa_b2, 16, tid, NT);
    cp_smem(sw->oa_g, oa_g, 16, tid, NT);
    cp_smem(sw->oa_bln, oa_bln, 16, tid, NT);
    cp_smem(sw->g_w1, g_w1, 3 * 32, tid, NT);
    cp_smem(sw->g_b1, g_b1, 32, tid, NT);
    cp_smem(sw->g_w2, g_w2, 32 * 16, tid, NT);
    cp_smem(sw->g_b2, g_b2, 16, tid, NT);
    cp_smem(sw->g_g, g_g, 16, tid, NT);
    cp_smem(sw->g_bln, g_bln, 16, tid, NT);
    cp_smem(sw->m_w1, m_w1, 48 * 32, tid, NT);
    cp_smem(sw->m_b1, m_b1, 32, tid, NT);
    cp_smem(sw->m_w2, m_w2, 32 * 32, tid, NT);
    cp_smem(sw->m_b2, m_b2, 32, tid, NT);
    cp_smem(sw->m_w3, m_w3, 32 * 2, tid, NT);
    if (tid < 2) sw->m_b3[tid] = m_b3[tid];
    __syncthreads();

    const int r = blockIdx.x * NT + tid;
    if (r >= B) return;

    // per-thread row in smem; stride 127 ≡ -1 (mod 32) → conflict-free
    const float* x = xs + tid * OBS;

    // ---------------- self encoder: 4 -> 32 -> 16 ----------------
    float self_out[16];
    {
        float in4[4];
#pragma unroll
        for (int k = 0; k < 4; k++) in4[k] = x[k];
        u64 a1[16];
        dense_packed<4, 16>(in4, sw->en_w1, sw->en_b1, a1);
        float h[32];
        relu_unpack<16>(a1, h);
        u64 a2[8];
        dense_packed<32, 8>(h, sw->en_w2, sw->en_b2, a2);
        relu_unpack<8>(a2, self_out);
    }

    u64 sp[8];
#pragma unroll
    for (int p = 0; p < 8; p++) sp[p] = f2pack(self_out[2 * p], self_out[2 * p + 1]);

    // ---------------- other-agent attention (15 entities, 5-d in) ----------------
    float other_out[16];
    {
        float mmax = -__int_as_float(0x7f800000);
        float l = 0.f;
        u64 att[8];
#pragma unroll
        for (int p = 0; p < 8; p++) att[p] = 0ull;

#pragma unroll 1
        for (int i = 0; i < 15; i++) {
            float in5[5];
            in5[0] = x[4 + 2 * i];
            in5[1] = x[5 + 2 * i];
            in5[2] = x[34 + 2 * i];
            in5[3] = x[35 + 2 * i];
            in5[4] = x[64 + i];

            u64 a1[16];
            dense_packed<5, 16>(in5, sw->oa_w1, sw->oa_b1, a1);
            float h[32];
            relu_unpack<16>(a1, h);
            u64 a2[8];
            dense_packed<32, 8>(h, sw->oa_w2, sw->oa_b2, a2);
            float ef[16];
            relu_unpack<8>(a2, ef);
            u64 e[8];
#pragma unroll
            for (int p = 0; p < 8; p++) e[p] = f2pack(ef[2 * p], ef[2 * p + 1]);

            u64 d2 = f2mul(sp[0], e[0]);
#pragma unroll
            for (int p = 1; p < 8; p++) d2 = f2fma(sp[p], e[p], d2);
            float dl, dh; f2unpack(d2, dl, dh);
            float s = (dl + dh) * 0.25f;

            float nm = fmaxf(mmax, s);
            float corr = __expf(mmax - nm);
            float pw   = __expf(s - nm);
            mmax = nm;
            l = l * corr + pw;
            u64 c2 = f2splat(corr), p2 = f2splat(pw);
#pragma unroll
            for (int p = 0; p < 8; p++) att[p] = f2fma(c2, att[p], f2mul(p2, e[p]));
        }

        float inv = __fdividef(1.f, l);
        float a16[16];
#pragma unroll
        for (int p = 0; p < 8; p++) {
            float a, b; f2unpack(att[p], a, b);
            a16[2 * p] = a * inv; a16[2 * p + 1] = b * inv;
        }
        float mu = 0.f;
#pragma unroll
        for (int d = 0; d < 16; d++) mu += a16[d];
        mu *= (1.f / 16.f);
        float var = 0.f;
#pragma unroll
        for (int d = 0; d < 16; d++) { float c = a16[d] - mu; var += c * c; }
        var *= (1.f / 16.f);
        float rs = rsqrtf(var + 1e-5f);
#pragma unroll
        for (int d = 0; d < 16; d++)
            other_out[d] = fmaxf((a16[d] - mu) * rs * sw->oa_g[d] + sw->oa_bln[d], 0.f);
    }

    // ---------------- food attention (16 entities, 3-d in) ----------------
    float food_out[16];
    {
        float mmax = -__int_as_float(0x7f800000);
        float l = 0.f;
        u64 att[8];
#pragma unroll
        for (int p = 0; p < 8; p++) att[p] = 0ull;

#pragma unroll 1
        for (int i = 0; i < 16; i++) {
            float in3[3];
            in3[0] = x[79 + 3 * i];
            in3[1] = x[80 + 3 * i];
            in3[2] = x[81 + 3 * i];

            u64 a1[16];
            dense_packed<3, 16>(in3, sw->g_w1, sw->g_b1, a1);
            float h[32];
            relu_unpack<16>(a1, h);
            u64 a2[8];
            dense_packed<32, 8>(h, sw->g_w2, sw->g_b2, a2);
            float ef[16];
            relu_unpack<8>(a2, ef);
            u64 e[8];
#pragma unroll
            for (int p = 0; p < 8; p++) e[p] = f2pack(ef[2 * p], ef[2 * p + 1]);

            u64 d2 = f2mul(sp[0], e[0]);
#pragma unroll
            for (int p = 1; p < 8; p++) d2 = f2fma(sp[p], e[p], d2);
            float dl, dh; f2unpack(d2, dl, dh);
            float s = (dl + dh) * 0.25f;

            float nm = fmaxf(mmax, s);
            float corr = __expf(mmax - nm);
            float pw   = __expf(s - nm);
            mmax = nm;
            l = l * corr + pw;
            u64 c2 = f2splat(corr), p2 = f2splat(pw);
#pragma unroll
            for (int p = 0; p < 8; p++) att[p] = f2fma(c2, att[p], f2mul(p2, e[p]));
        }

        float inv = __fdividef(1.f, l);
        float a16[16];
#pragma unroll
        for (int p = 0; p < 8; p++) {
            float a, b; f2unpack(att[p], a, b);
            a16[2 * p] = a * inv; a16[2 * p + 1] = b * inv;
        }
        float mu = 0.f;
#pragma unroll
        for (int d = 0; d < 16; d++) mu += a16[d];
        mu *= (1.f / 16.f);
        float var = 0.f;
#pragma unroll
        for (int d = 0; d < 16; d++) { float c = a16[d] - mu; var += c * c; }
        var *= (1.f / 16.f);
        float rs = rsqrtf(var + 1e-5f);
#pragma unroll
        for (int d = 0; d < 16; d++)
            food_out[d] = fmaxf((a16[d] - mu) * rs * sw->g_g[d] + sw->g_bln[d], 0.f);
    }

    // ---------------- merge head: 48 -> 32 -> 32 -> 2 ----------------
    float mg[48];
#pragma unroll
    for (int d = 0; d < 16; d++) {
        mg[d] = self_out[d];
        mg[16 + d] = food_out[d];
        mg[32 + d] = other_out[d];
    }

    u64 acc1[16];
    dense_packed<48, 16>(mg, sw->m_w1, sw->m_b1, acc1);
    float h1[32];
    leaky_unpack<16>(acc1, h1);

    u64 acc2[16];
    dense_packed<32, 16>(h1, sw->m_w2, sw->m_b2, acc2);
    float h2[32];
    leaky_unpack<16>(acc2, h2);

    u64 acc3[1];
    dense_packed<32, 1>(h2, sw->m_w3, sw->m_b3, acc3);
    float o0, o1; f2unpack(acc3[0], o0, o1);
    o0 = tanhf(o0);
    o1 = tanhf(o1);

    reinterpret_cast<float2*>(out)[r] = make_float2(o0, o1);
}

extern "C" void kernel_launch(void* const* d_in, const int* in_sizes, int n_in,
                              void* d_out, int out_size) {
    const float* s_in = (const float*)d_in[0];
    const int B = in_sizes[0] / OBS;
    const size_t shbytes = (size_t)NT * OBS * sizeof(float) + sizeof(SW);
    cudaFuncSetAttribute(actor_kernel,
                         cudaFuncAttributeMaxDynamicSharedMemorySize, (int)shbytes);
    dim3 grid((B + NT - 1) / NT), block(NT);
    actor_kernel<<<grid, block, shbytes>>>(
        s_in,
        (const float*)d_in[1],  (const float*)d_in[2],
        (const float*)d_in[3],  (const float*)d_in[4],
        (const float*)d_in[5],  (const float*)d_in[6],
        (const float*)d_in[7],  (const float*)d_in[8],
        (const float*)d_in[9],  (const float*)d_in[10],
        (const float*)d_in[11], (const float*)d_in[12],
        (const float*)d_in[13], (const float*)d_in[14],
        (const float*)d_in[15], (const float*)d_in[16],
        (const float*)d_in[17], (const float*)d_in[18],
        (const float*)d_in[19], (const float*)d_in[20],
        (const float*)d_in[21], (const float*)d_in[22],
        (float*)d_out, B);
}

// round 3
// speedup vs baseline: 3.7218x; 1.6101x over previous
#include <cuda_runtime.h>
#include <math.h>

// ============================================================================
// Actor_att1 — R3: two threads cooperate per row (split-N layer1 / split-K
// layer2 + shfl_xor butterfly), packed f32x2 math, 16 warps/SM.
// ============================================================================

typedef unsigned long long u64;
#define DINL __device__ __forceinline__

DINL u64 f2pack(float lo, float hi) {
    u64 d; asm("mov.b64 %0, {%1, %2};" : "=l"(d) : "f"(lo), "f"(hi)); return d;
}
DINL u64 f2splat(float v) {
    u64 d; asm("mov.b64 %0, {%1, %1};" : "=l"(d) : "f"(v)); return d;
}
DINL void f2unpack(u64 v, float& lo, float& hi) {
    asm("mov.b64 {%0, %1}, %2;" : "=f"(lo), "=f"(hi) : "l"(v));
}
DINL u64 f2fma(u64 a, u64 b, u64 c) {
    u64 d; asm("fma.rn.f32x2 %0, %1, %2, %3;" : "=l"(d) : "l"(a), "l"(b), "l"(c)); return d;
}
DINL u64 f2mul(u64 a, u64 b) {
    u64 d; asm("mul.rn.f32x2 %0, %1, %2;" : "=l"(d) : "l"(a), "l"(b)); return d;
}
DINL u64 f2add(u64 a, u64 b) {
    u64 d; asm("add.rn.f32x2 %0, %1, %2;" : "=l"(d) : "l"(a), "l"(b)); return d;
}
DINL u64 shfl64(u64 v) {
    return __shfl_xor_sync(0xffffffffu, v, 1);
}

// ---- layer 1 (full-K, split-N): thread computes 16 of 32 hidden units ----
// w row-major [K][32]; this thread's columns = [hofs, hofs+16) floats.
template<int K>
DINL void dense1_half(const float* in, const float* __restrict__ w,
                      const float* __restrict__ b, int hofs, u64 acc[8]) {
    const ulonglong2* bp = reinterpret_cast<const ulonglong2*>(b + hofs);
#pragma unroll
    for (int q = 0; q < 4; q++) {
        ulonglong2 t = bp[q];
        acc[2 * q] = t.x; acc[2 * q + 1] = t.y;
    }
#pragma unroll
    for (int k = 0; k < K; k++) {
        u64 xs = f2splat(in[k]);
        const ulonglong2* wr = reinterpret_cast<const ulonglong2*>(w + k * 32 + hofs);
#pragma unroll
        for (int q = 0; q < 4; q++) {
            ulonglong2 t = wr[q];
            acc[2 * q]     = f2fma(xs, t.x, acc[2 * q]);
            acc[2 * q + 1] = f2fma(xs, t.y, acc[2 * q + 1]);
        }
    }
}

// ---- layer 2 (split-K, 16 outs): thread owns hidden dims [16h,16h+16).
// mine[4] = partials for MY 4 output pairs (float cols [8h,8h+8)),
// theirs[4] = partials for partner's pairs. After butterfly, mine[] holds
// the complete outputs for my pairs. w2 row-major [32][16].
DINL void dense2_half(const float* hloc, const float* __restrict__ w2,
                      const float* __restrict__ b2, int h, u64 mine[4]) {
    const int mofs = h * 8, tofs = 8 - h * 8;
    u64 theirs[4];
    {
        const ulonglong2* bp = reinterpret_cast<const ulonglong2*>(b2 + mofs);
        ulonglong2 t0 = bp[0], t1 = bp[1];
        mine[0] = t0.x; mine[1] = t0.y; mine[2] = t1.x; mine[3] = t1.y;
        theirs[0] = theirs[1] = theirs[2] = theirs[3] = 0ull;
    }
#pragma unroll
    for (int j = 0; j < 16; j++) {
        const int k = h * 16 + j;
        u64 xs = f2splat(hloc[j]);
        const ulonglong2* wm = reinterpret_cast<const ulonglong2*>(w2 + k * 16 + mofs);
        const ulonglong2* wt = reinterpret_cast<const ulonglong2*>(w2 + k * 16 + tofs);
        ulonglong2 m0 = wm[0], m1 = wm[1], t0 = wt[0], t1 = wt[1];
        mine[0] = f2fma(xs, m0.x, mine[0]);
        mine[1] = f2fma(xs, m0.y, mine[1]);
        mine[2] = f2fma(xs, m1.x, mine[2]);
        mine[3] = f2fma(xs, m1.y, mine[3]);
        theirs[0] = f2fma(xs, t0.x, theirs[0]);
        theirs[1] = f2fma(xs, t0.y, theirs[1]);
        theirs[2] = f2fma(xs, t1.x, theirs[2]);
        theirs[3] = f2fma(xs, t1.y, theirs[3]);
    }
#pragma unroll
    for (int p = 0; p < 4; p++) mine[p] = f2add(mine[p], shfl64(theirs[p]));
}

// ---- merge-head dense (32 outs, split-K over 16 inputs this thread owns,
// k-index = kbase+j; split-N via mine/theirs). w row-major [*][32]. ----
DINL void dense32_accum(const float* xloc, const float* __restrict__ w,
                        int kbase, int h, u64 mine[8], u64 theirs[8]) {
    const int mofs = h * 16, tofs = 16 - h * 16;
#pragma unroll
    for (int j = 0; j < 8; j++) {
        const int k = kbase + j;
        u64 xs = f2splat(xloc[j]);
        const ulonglong2* wm = reinterpret_cast<const ulonglong2*>(w + k * 32 + mofs);
        const ulonglong2* wt = reinterpret_cast<const ulonglong2*>(w + k * 32 + tofs);
#pragma unroll
        for (int q = 0; q < 4; q++) {
            ulonglong2 m = wm[q], t = wt[q];
            mine[2 * q]     = f2fma(xs, m.x, mine[2 * q]);
            mine[2 * q + 1] = f2fma(xs, m.y, mine[2 * q + 1]);
            theirs[2 * q]     = f2fma(xs, t.x, theirs[2 * q]);
            theirs[2 * q + 1] = f2fma(xs, t.y, theirs[2 * q + 1]);
        }
    }
}

struct SW {
    float en_w1[4 * 32];  float en_b1[32];  float en_w2[32 * 16]; float en_b2[16];
    float oa_w1[5 * 32];  float oa_b1[32];  float oa_w2[32 * 16]; float oa_b2[16];
    float oa_g[16];       float oa_bln[16];
    float g_w1[3 * 32];   float g_b1[32];   float g_w2[32 * 16];  float g_b2[16];
    float g_g[16];        float g_bln[16];
    float m_w1[48 * 32];  float m_b1[32];   float m_w2[32 * 32];  float m_b2[32];
    float m_w3[32 * 2];   float m_b3[16];
};

DINL void cp_smem(float* dst, const float* __restrict__ src, int n, int tid, int nt) {
    for (int i = tid; i < n; i += nt) dst[i] = src[i];
}

#define NT 256
#define ROWS 128
#define OBS 127

__global__ void __launch_bounds__(NT, 2)
actor_kernel(const float* __restrict__ s_in,
             const float* __restrict__ en_w1, const float* __restrict__ en_b1,
             const float* __restrict__ en_w2, const float* __restrict__ en_b2,
             const float* __restrict__ oa_w1, const float* __restrict__ oa_b1,
             const float* __restrict__ oa_w2, const float* __restrict__ oa_b2,
             const float* __restrict__ oa_g,  const float* __restrict__ oa_bln,
             const float* __restrict__ g_w1,  const float* __restrict__ g_b1,
             const float* __restrict__ g_w2,  const float* __restrict__ g_b2,
             const float* __restrict__ g_g,   const float* __restrict__ g_bln,
             const float* __restrict__ m_w1,  const float* __restrict__ m_b1,
             const float* __restrict__ m_w2,  const float* __restrict__ m_b2,
             const float* __restrict__ m_w3,  const float* __restrict__ m_b3,
             float* __restrict__ out, int B)
{
    extern __shared__ __align__(16) float smem[];
    float* xs = smem;                               // ROWS * OBS floats
    SW* sw = reinterpret_cast<SW*>(smem + ROWS * OBS);

    const int tid = threadIdx.x;

    // ---- coalesced input staging ----
    {
        const size_t base = (size_t)blockIdx.x * ROWS * OBS;
        const float4* src4 = reinterpret_cast<const float4*>(s_in + base);
        float4* dst4 = reinterpret_cast<float4*>(xs);
        const size_t totElems = (size_t)B * OBS;
        const int n4avail = (int)((totElems - base) / 4);
        const int n4 = min(ROWS * OBS / 4, n4avail);   // 4064 normally
#pragma unroll 2
        for (int i = tid; i < n4; i += NT) dst4[i] = src4[i];
    }

    cp_smem(sw->en_w1, en_w1, 4 * 32, tid, NT);
    cp_smem(sw->en_b1, en_b1, 32, tid, NT);
    cp_smem(sw->en_w2, en_w2, 32 * 16, tid, NT);
    cp_smem(sw->en_b2, en_b2, 16, tid, NT);
    cp_smem(sw->oa_w1, oa_w1, 5 * 32, tid, NT);
    cp_smem(sw->oa_b1, oa_b1, 32, tid, NT);
    cp_smem(sw->oa_w2, oa_w2, 32 * 16, tid, NT);
    cp_smem(sw->oa_b2, oa_b2, 16, tid, NT);
    cp_smem(sw->oa_g, oa_g, 16, tid, NT);
    cp_smem(sw->oa_bln, oa_bln, 16, tid, NT);
    cp_smem(sw->g_w1, g_w1, 3 * 32, tid, NT);
    cp_smem(sw->g_b1, g_b1, 32, tid, NT);
    cp_smem(sw->g_w2, g_w2, 32 * 16, tid, NT);
    cp_smem(sw->g_b2, g_b2, 16, tid, NT);
    cp_smem(sw->g_g, g_g, 16, tid, NT);
    cp_smem(sw->g_bln, g_bln, 16, tid, NT);
    cp_smem(sw->m_w1, m_w1, 48 * 32, tid, NT);
    cp_smem(sw->m_b1, m_b1, 32, tid, NT);
    cp_smem(sw->m_w2, m_w2, 32 * 32, tid, NT);
    cp_smem(sw->m_b2, m_b2, 32, tid, NT);
    cp_smem(sw->m_w3, m_w3, 32 * 2, tid, NT);
    if (tid < 2) sw->m_b3[tid] = m_b3[tid];
    __syncthreads();

    const int rloc = tid >> 1;          // local row 0..127
    const int h = tid & 1;              // which half of the pair
    const int row = blockIdx.x * ROWS + rloc;
    if (row >= B) return;

    const float* x = xs + rloc * OBS;   // pair lanes share addresses (broadcast)
    const int hofs = h * 16;            // layer-1 column offset (floats)

    // ---------------- self encoder: 4 -> 32 -> 16 (half result) ----------------
    u64 sp[4];                           // my 4 output pairs, packed & relu'd
    float self_half[8];
    {
        float in4[4];
#pragma unroll
        for (int k = 0; k < 4; k++) in4[k] = x[k];
        u64 a1[8];
        dense1_half<4>(in4, sw->en_w1, sw->en_b1, hofs, a1);
        float hh[16];
#pragma unroll
        for (int q = 0; q < 8; q++) {
            float a, b2v; f2unpack(a1[q], a, b2v);
            hh[2 * q] = fmaxf(a, 0.f); hh[2 * q + 1] = fmaxf(b2v, 0.f);
        }
        u64 m[4];
        dense2_half(hh, sw->en_w2, sw->en_b2, h, m);
#pragma unroll
        for (int p = 0; p < 4; p++) {
            float a, b2v; f2unpack(m[p], a, b2v);
            a = fmaxf(a, 0.f); b2v = fmaxf(b2v, 0.f);
            self_half[2 * p] = a; self_half[2 * p + 1] = b2v;
            sp[p] = f2pack(a, b2v);
        }
    }

    // ---------------- attention helper state ----------------
    float other_half[8], food_half[8];

    // ======== other-agent attention: 15 entities, 5-d input ========
    {
        float mmax = -__int_as_float(0x7f800000);
        float l = 0.f;
        u64 att[4] = {0ull, 0ull, 0ull, 0ull};

#pragma unroll 1
        for (int i = 0; i < 15; i++) {
            float in5[5];
            in5[0] = x[4 + 2 * i];
            in5[1] = x[5 + 2 * i];
            in5[2] = x[34 + 2 * i];
            in5[3] = x[35 + 2 * i];
            in5[4] = x[64 + i];

            u64 a1[8];
            dense1_half<5>(in5, sw->oa_w1, sw->oa_b1, hofs, a1);
            float hh[16];
#pragma unroll
            for (int q = 0; q < 8; q++) {
                float a, b2v; f2unpack(a1[q], a, b2v);
                hh[2 * q] = fmaxf(a, 0.f); hh[2 * q + 1] = fmaxf(b2v, 0.f);
            }
            u64 e[4];
            dense2_half(hh, sw->oa_w2, sw->oa_b2, h, e);
#pragma unroll
            for (int p = 0; p < 4; p++) {
                float a, b2v; f2unpack(e[p], a, b2v);
                e[p] = f2pack(fmaxf(a, 0.f), fmaxf(b2v, 0.f));
            }

            // score: my half-dot + cross add
            u64 d2 = f2mul(sp[0], e[0]);
#pragma unroll
            for (int p = 1; p < 4; p++) d2 = f2fma(sp[p], e[p], d2);
            float dl, dh; f2unpack(d2, dl, dh);
            float sh = dl + dh;
            float s = (sh + __shfl_xor_sync(0xffffffffu, sh, 1)) * 0.25f;

            float nm = fmaxf(mmax, s);
            float corr = __expf(mmax - nm);
            float pw   = __expf(s - nm);
            mmax = nm;
            l = l * corr + pw;
            u64 c2 = f2splat(corr), p2 = f2splat(pw);
#pragma unroll
            for (int p = 0; p < 4; p++) att[p] = f2fma(c2, att[p], f2mul(p2, e[p]));
        }

        float inv = __fdividef(1.f, l);
        float a8[8];
#pragma unroll
        for (int p = 0; p < 4; p++) {
            float a, b2v; f2unpack(att[p], a, b2v);
            a8[2 * p] = a * inv; a8[2 * p + 1] = b2v * inv;
        }
        float sm = 0.f;
#pragma unroll
        for (int d = 0; d < 8; d++) sm += a8[d];
        float mu = (sm + __shfl_xor_sync(0xffffffffu, sm, 1)) * (1.f / 16.f);
        float vr = 0.f;
#pragma unroll
        for (int d = 0; d < 8; d++) { float c = a8[d] - mu; vr += c * c; }
        float var = (vr + __shfl_xor_sync(0xffffffffu, vr, 1)) * (1.f / 16.f);
        float rs = rsqrtf(var + 1e-5f);
#pragma unroll
        for (int d = 0; d < 8; d++) {
            int gd = h * 8 + d;
            other_half[d] = fmaxf((a8[d] - mu) * rs * sw->oa_g[gd] + sw->oa_bln[gd], 0.f);
        }
    }

    // ======== food attention: 16 entities, 3-d input ========
    {
        float mmax = -__int_as_float(0x7f800000);
        float l = 0.f;
        u64 att[4] = {0ull, 0ull, 0ull, 0ull};

#pragma unroll 1
        for (int i = 0; i < 16; i++) {
            float in3[3];
            in3[0] = x[79 + 3 * i];
            in3[1] = x[80 + 3 * i];
            in3[2] = x[81 + 3 * i];

            u64 a1[8];
            dense1_half<3>(in3, sw->g_w1, sw->g_b1, hofs, a1);
            float hh[16];
#pragma unroll
            for (int q = 0; q < 8; q++) {
                float a, b2v; f2unpack(a1[q], a, b2v);
                hh[2 * q] = fmaxf(a, 0.f); hh[2 * q + 1] = fmaxf(b2v, 0.f);
            }
            u64 e[4];
            dense2_half(hh, sw->g_w2, sw->g_b2, h, e);
#pragma unroll
            for (int p = 0; p < 4; p++) {
                float a, b2v; f2unpack(e[p], a, b2v);
                e[p] = f2pack(fmaxf(a, 0.f), fmaxf(b2v, 0.f));
            }

            u64 d2 = f2mul(sp[0], e[0]);
#pragma unroll
            for (int p = 1; p < 4; p++) d2 = f2fma(sp[p], e[p], d2);
            float dl, dh; f2unpack(d2, dl, dh);
            float sh = dl + dh;
            float s = (sh + __shfl_xor_sync(0xffffffffu, sh, 1)) * 0.25f;

            float nm = fmaxf(mmax, s);
            float corr = __expf(mmax - nm);
            float pw   = __expf(s - nm);
            mmax = nm;
            l = l * corr + pw;
            u64 c2 = f2splat(corr), p2 = f2splat(pw);
#pragma unroll
            for (int p = 0; p < 4; p++) att[p] = f2fma(c2, att[p], f2mul(p2, e[p]));
        }

        float inv = __fdividef(1.f, l);
        float a8[8];
#pragma unroll
        for (int p = 0; p < 4; p++) {
            float a, b2v; f2unpack(att[p], a, b2v);
            a8[2 * p] = a * inv; a8[2 * p + 1] = b2v * inv;
        }
        float sm = 0.f;
#pragma unroll
        for (int d = 0; d < 8; d++) sm += a8[d];
        float mu = (sm + __shfl_xor_sync(0xffffffffu, sm, 1)) * (1.f / 16.f);
        float vr = 0.f;
#pragma unroll
        for (int d = 0; d < 8; d++) { float c = a8[d] - mu; vr += c * c; }
        float var = (vr + __shfl_xor_sync(0xffffffffu, vr, 1)) * (1.f / 16.f);
        float rs = rsqrtf(var + 1e-5f);
#pragma unroll
        for (int d = 0; d < 8; d++) {
            int gd = h * 8 + d;
            food_half[d] = fmaxf((a8[d] - mu) * rs * sw->g_g[gd] + sw->g_bln[gd], 0.f);
        }
    }

    // ---------------- merge head: 48 -> 32 -> 32 -> 2 ----------------
    // Layer m1: split-K (my 24 of 48 inputs), split-N via mine/theirs.
    float h1loc[16];
    {
        u64 mine[8], theirs[8];
        const ulonglong2* bp = reinterpret_cast<const ulonglong2*>(sw->m_b1 + h * 16);
#pragma unroll
        for (int q = 0; q < 4; q++) {
            ulonglong2 t = bp[q];
            mine[2 * q] = t.x; mine[2 * q + 1] = t.y;
            theirs[2 * q] = 0ull; theirs[2 * q + 1] = 0ull;
        }
        dense32_accum(self_half,  sw->m_w1, h * 8,      h, mine, theirs);
        dense32_accum(food_half,  sw->m_w1, 16 + h * 8, h, mine, theirs);
        dense32_accum(other_half, sw->m_w1, 32 + h * 8, h, mine, theirs);
#pragma unroll
        for (int p = 0; p < 8; p++) mine[p] = f2add(mine[p], shfl64(theirs[p]));
#pragma unroll
        for (int p = 0; p < 8; p++) {
            float a, b2v; f2unpack(mine[p], a, b2v);
            h1loc[2 * p]     = fmaxf(a, 0.01f * a);
            h1loc[2 * p + 1] = fmaxf(b2v, 0.01f * b2v);
        }
    }

    // Layer m2: my 16 inputs = dims [16h,16h+16) (exactly h1loc).
    float h2loc[16];
    {
        u64 mine[8], theirs[8];
        const ulonglong2* bp = reinterpret_cast<const ulonglong2*>(sw->m_b2 + h * 16);
#pragma unroll
        for (int q = 0; q < 4; q++) {
            ulonglong2 t = bp[q];
            mine[2 * q] = t.x; mine[2 * q + 1] = t.y;
            theirs[2 * q] = 0ull; theirs[2 * q + 1] = 0ull;
        }
        dense32_accum(h1loc,     sw->m_w2, 16 * h,     h, mine, theirs);
        dense32_accum(h1loc + 8, sw->m_w2, 16 * h + 8, h, mine, theirs);
#pragma unroll
        for (int p = 0; p < 8; p++) mine[p] = f2add(mine[p], shfl64(theirs[p]));
#pragma unroll
        for (int p = 0; p < 8; p++) {
            float a, b2v; f2unpack(mine[p], a, b2v);
            h2loc[2 * p]     = fmaxf(a, 0.01f * a);
            h2loc[2 * p + 1] = fmaxf(b2v, 0.01f * b2v);
        }
    }

    // Layer m3: 32 -> 2. Each thread sums its 16 k's; butterfly once.
    {
        u64 acc = (h == 0) ? *reinterpret_cast<const u64*>(sw->m_b3) : 0ull;
        const u64* w3 = reinterpret_cast<const u64*>(sw->m_w3);
#pragma unroll
        for (int j = 0; j < 16; j++) {
            const int k = h * 16 + j;
            acc = f2fma(f2splat(h2loc[j]), w3[k], acc);
        }
        u64 t = shfl64(acc);
        acc = f2add(acc, t);
        if (h == 0) {
            float o0, o1; f2unpack(acc, o0, o1);
            reinterpret_cast<float2*>(out)[row] = make_float2(tanhf(o0), tanhf(o1));
        }
    }
}

extern "C" void kernel_launch(void* const* d_in, const int* in_sizes, int n_in,
                              void* d_out, int out_size) {
    const float* s_in = (const float*)d_in[0];
    const int B = in_sizes[0] / OBS;
    const size_t shbytes = (size_t)ROWS * OBS * sizeof(float) + sizeof(SW);
    cudaFuncSetAttribute(actor_kernel,
                         cudaFuncAttributeMaxDynamicSharedMemorySize, (int)shbytes);
    dim3 grid((B + ROWS - 1) / ROWS), block(NT);
    actor_kernel<<<grid, block, shbytes>>>(
        s_in,
        (const float*)d_in[1],  (const float*)d_in[2],
        (const float*)d_in[3],  (const float*)d_in[4],
        (const float*)d_in[5],  (const float*)d_in[6],
        (const float*)d_in[7],  (const float*)d_in[8],
        (const float*)d_in[9],  (const float*)d_in[10],
        (const float*)d_in[11], (const float*)d_in[12],
        (const float*)d_in[13], (const float*)d_in[14],
        (const float*)d_in[15], (const float*)d_in[16],
        (const float*)d_in[17], (const float*)d_in[18],
        (const float*)d_in[19], (const float*)d_in[20],
        (const float*)d_in[21], (const float*)d_in[22],
        (float*)d_out, B);
}

// round 7
// speedup vs baseline: 5.8627x; 1.5752x over previous
#include <cuda_runtime.h>
#include <math.h>

// ============================================================================
// Actor_att1 — R4: 2 threads per row (split-N/split-K + shfl butterfly)
// AND 2 rows per thread (weight-LDS amortization). Packed f32x2 math.
// ============================================================================

typedef unsigned long long u64;
#define DINL __device__ __forceinline__

DINL u64 f2pack(float lo, float hi) {
    u64 d; asm("mov.b64 %0, {%1, %2};" : "=l"(d) : "f"(lo), "f"(hi)); return d;
}
DINL u64 f2splat(float v) {
    u64 d; asm("mov.b64 %0, {%1, %1};" : "=l"(d) : "f"(v)); return d;
}
DINL void f2unpack(u64 v, float& lo, float& hi) {
    asm("mov.b64 {%0, %1}, %2;" : "=f"(lo), "=f"(hi) : "l"(v));
}
DINL u64 f2fma(u64 a, u64 b, u64 c) {
    u64 d; asm("fma.rn.f32x2 %0, %1, %2, %3;" : "=l"(d) : "l"(a), "l"(b), "l"(c)); return d;
}
DINL u64 f2mul(u64 a, u64 b) {
    u64 d; asm("mul.rn.f32x2 %0, %1, %2;" : "=l"(d) : "l"(a), "l"(b)); return d;
}
DINL u64 f2add(u64 a, u64 b) {
    u64 d; asm("add.rn.f32x2 %0, %1, %2;" : "=l"(d) : "l"(a), "l"(b)); return d;
}
DINL u64 shfl64(u64 v) { return __shfl_xor_sync(0xffffffffu, v, 1); }
DINL float shflf(float v) { return __shfl_xor_sync(0xffffffffu, v, 1); }

// ---- layer 1 (full-K, split-N), 2 rows: weights loaded once ----
template<int K>
DINL void dense1_2r(const float* in0, const float* in1,
                    const float* __restrict__ w, const float* __restrict__ b,
                    int hofs, u64 acc0[8], u64 acc1[8]) {
    const ulonglong2* bp = reinterpret_cast<const ulonglong2*>(b + hofs);
#pragma unroll
    for (int q = 0; q < 4; q++) {
        ulonglong2 t = bp[q];
        acc0[2 * q] = t.x; acc0[2 * q + 1] = t.y;
        acc1[2 * q] = t.x; acc1[2 * q + 1] = t.y;
    }
#pragma unroll
    for (int k = 0; k < K; k++) {
        u64 xs0 = f2splat(in0[k]);
        u64 xs1 = f2splat(in1[k]);
        const ulonglong2* wr = reinterpret_cast<const ulonglong2*>(w + k * 32 + hofs);
#pragma unroll
        for (int q = 0; q < 4; q++) {
            ulonglong2 t = wr[q];
            acc0[2 * q]     = f2fma(xs0, t.x, acc0[2 * q]);
            acc0[2 * q + 1] = f2fma(xs0, t.y, acc0[2 * q + 1]);
            acc1[2 * q]     = f2fma(xs1, t.x, acc1[2 * q]);
            acc1[2 * q + 1] = f2fma(xs1, t.y, acc1[2 * q + 1]);
        }
    }
}

// ---- layer 2 (split-K, 16 outs), 2 rows: weights loaded once ----
DINL void dense2_2r(const float* h0, const float* h1,
                    const float* __restrict__ w2, const float* __restrict__ b2,
                    int h, u64 mine0[4], u64 mine1[4]) {
    const int mofs = h * 8, tofs = 8 - h * 8;
    u64 th0[4], th1[4];
    {
        const ulonglong2* bp = reinterpret_cast<const ulonglong2*>(b2 + mofs);
        ulonglong2 t0 = bp[0], t1 = bp[1];
        mine0[0] = t0.x; mine0[1] = t0.y; mine0[2] = t1.x; mine0[3] = t1.y;
        mine1[0] = t0.x; mine1[1] = t0.y; mine1[2] = t1.x; mine1[3] = t1.y;
#pragma unroll
        for (int p = 0; p < 4; p++) { th0[p] = 0ull; th1[p] = 0ull; }
    }
#pragma unroll
    for (int j = 0; j < 16; j++) {
        const int k = h * 16 + j;
        u64 xs0 = f2splat(h0[j]);
        u64 xs1 = f2splat(h1[j]);
        const ulonglong2* wm = reinterpret_cast<const ulonglong2*>(w2 + k * 16 + mofs);
        const ulonglong2* wt = reinterpret_cast<const ulonglong2*>(w2 + k * 16 + tofs);
        ulonglong2 m0 = wm[0], m1 = wm[1], t0 = wt[0], t1 = wt[1];
        mine0[0] = f2fma(xs0, m0.x, mine0[0]);
        mine0[1] = f2fma(xs0, m0.y, mine0[1]);
        mine0[2] = f2fma(xs0, m1.x, mine0[2]);
        mine0[3] = f2fma(xs0, m1.y, mine0[3]);
        mine1[0] = f2fma(xs1, m0.x, mine1[0]);
        mine1[1] = f2fma(xs1, m0.y, mine1[1]);
        mine1[2] = f2fma(xs1, m1.x, mine1[2]);
        mine1[3] = f2fma(xs1, m1.y, mine1[3]);
        th0[0] = f2fma(xs0, t0.x, th0[0]);
        th0[1] = f2fma(xs0, t0.y, th0[1]);
        th0[2] = f2fma(xs0, t1.x, th0[2]);
        th0[3] = f2fma(xs0, t1.y, th0[3]);
        th1[0] = f2fma(xs1, t0.x, th1[0]);
        th1[1] = f2fma(xs1, t0.y, th1[1]);
        th1[2] = f2fma(xs1, t1.x, th1[2]);
        th1[3] = f2fma(xs1, t1.y, th1[3]);
    }
#pragma unroll
    for (int p = 0; p < 4; p++) {
        mine0[p] = f2add(mine0[p], shfl64(th0[p]));
        mine1[p] = f2add(mine1[p], shfl64(th1[p]));
    }
}

// ---- merge-head dense accumulate (32 outs, split-K + split-N), 2 rows ----
DINL void dense32_2r(const float* x0, const float* x1, const float* __restrict__ w,
                     int kbase, int h,
                     u64 m0[8], u64 m1[8], u64 t0a[8], u64 t1a[8]) {
    const int mofs = h * 16, tofs = 16 - h * 16;
#pragma unroll
    for (int j = 0; j < 8; j++) {
        const int k = kbase + j;
        u64 xs0 = f2splat(x0[j]);
        u64 xs1 = f2splat(x1[j]);
        const ulonglong2* wm = reinterpret_cast<const ulonglong2*>(w + k * 32 + mofs);
        const ulonglong2* wt = reinterpret_cast<const ulonglong2*>(w + k * 32 + tofs);
#pragma unroll
        for (int q = 0; q < 4; q++) {
            ulonglong2 m = wm[q], t = wt[q];
            m0[2 * q]     = f2fma(xs0, m.x, m0[2 * q]);
            m0[2 * q + 1] = f2fma(xs0, m.y, m0[2 * q + 1]);
            m1[2 * q]     = f2fma(xs1, m.x, m1[2 * q]);
            m1[2 * q + 1] = f2fma(xs1, m.y, m1[2 * q + 1]);
            t0a[2 * q]     = f2fma(xs0, t.x, t0a[2 * q]);
            t0a[2 * q + 1] = f2fma(xs0, t.y, t0a[2 * q + 1]);
            t1a[2 * q]     = f2fma(xs1, t.x, t1a[2 * q]);
            t1a[2 * q + 1] = f2fma(xs1, t.y, t1a[2 * q + 1]);
        }
    }
}

struct SW {
    float en_w1[4 * 32];  float en_b1[32];  float en_w2[32 * 16]; float en_b2[16];
    float oa_w1[5 * 32];  float oa_b1[32];  float oa_w2[32 * 16]; float oa_b2[16];
    float oa_g[16];       float oa_bln[16];
    float g_w1[3 * 32];   float g_b1[32];   float g_w2[32 * 16];  float g_b2[16];
    float g_g[16];        float g_bln[16];
    float m_w1[48 * 32];  float m_b1[32];   float m_w2[32 * 32];  float m_b2[32];
    float m_w3[32 * 2];   float m_b3[16];
};

DINL void cp_smem(float* dst, const float* __restrict__ src, int n, int tid, int nt) {
    for (int i = tid; i < n; i += nt) dst[i] = src[i];
}

#define NT 256
#define ROWS 256
#define OBS 127

__global__ void __launch_bounds__(NT, 1)
actor_kernel(const float* __restrict__ s_in,
             const float* __restrict__ en_w1, const float* __restrict__ en_b1,
             const float* __restrict__ en_w2, const float* __restrict__ en_b2,
             const float* __restrict__ oa_w1, const float* __restrict__ oa_b1,
             const float* __restrict__ oa_w2, const float* __restrict__ oa_b2,
             const float* __restrict__ oa_g,  const float* __restrict__ oa_bln,
             const float* __restrict__ g_w1,  const float* __restrict__ g_b1,
             const float* __restrict__ g_w2,  const float* __restrict__ g_b2,
             const float* __restrict__ g_g,   const float* __restrict__ g_bln,
             const float* __restrict__ m_w1,  const float* __restrict__ m_b1,
             const float* __restrict__ m_w2,  const float* __restrict__ m_b2,
             const float* __restrict__ m_w3,  const float* __restrict__ m_b3,
             float* __restrict__ out, int B)
{
    extern __shared__ __align__(16) float smem[];
    float* xs = smem;
    SW* sw = reinterpret_cast<SW*>(smem + ROWS * OBS);

    const int tid = threadIdx.x;

    {
        const size_t base = (size_t)blockIdx.x * ROWS * OBS;
        const float4* src4 = reinterpret_cast<const float4*>(s_in + base);
        float4* dst4 = reinterpret_cast<float4*>(xs);
        const int n4 = ROWS * OBS / 4;
#pragma unroll 4
        for (int i = tid; i < n4; i += NT) dst4[i] = src4[i];
    }

    cp_smem(sw->en_w1, en_w1, 4 * 32, tid, NT);
    cp_smem(sw->en_b1, en_b1, 32, tid, NT);
    cp_smem(sw->en_w2, en_w2, 32 * 16, tid, NT);
    cp_smem(sw->en_b2, en_b2, 16, tid, NT);
    cp_smem(sw->oa_w1, oa_w1, 5 * 32, tid, NT);
    cp_smem(sw->oa_b1, oa_b1, 32, tid, NT);
    cp_smem(sw->oa_w2, oa_w2, 32 * 16, tid, NT);
    cp_smem(sw->oa_b2, oa_b2, 16, tid, NT);
    cp_smem(sw->oa_g, oa_g, 16, tid, NT);
    cp_smem(sw->oa_bln, oa_bln, 16, tid, NT);
    cp_smem(sw->g_w1, g_w1, 3 * 32, tid, NT);
    cp_smem(sw->g_b1, g_b1, 32, tid, NT);
    cp_smem(sw->g_w2, g_w2, 32 * 16, tid, NT);
    cp_smem(sw->g_b2, g_b2, 16, tid, NT);
    cp_smem(sw->g_g, g_g, 16, tid, NT);
    cp_smem(sw->g_bln, g_bln, 16, tid, NT);
    cp_smem(sw->m_w1, m_w1, 48 * 32, tid, NT);
    cp_smem(sw->m_b1, m_b1, 32, tid, NT);
    cp_smem(sw->m_w2, m_w2, 32 * 32, tid, NT);
    cp_smem(sw->m_b2, m_b2, 32, tid, NT);
    cp_smem(sw->m_w3, m_w3, 32 * 2, tid, NT);
    if (tid < 2) sw->m_b3[tid] = m_b3[tid];
    __syncthreads();

    const int pr = tid >> 1;
    const int h = tid & 1;
    const int row0 = blockIdx.x * ROWS + 2 * pr;
    if (row0 >= B) return;

    const float* x0 = xs + (2 * pr) * OBS;
    const float* x1 = x0 + OBS;
    const int hofs = h * 16;

    // ---------------- self encoder ----------------
    u64 sp0[4], sp1[4];
    float self0[8], self1[8];
    {
        u64 a0[8], a1[8];
        dense1_2r<4>(x0, x1, sw->en_w1, sw->en_b1, hofs, a0, a1);
        float h0[16], h1[16];
#pragma unroll
        for (int q = 0; q < 8; q++) {
            float a, b; f2unpack(a0[q], a, b);
            h0[2 * q] = fmaxf(a, 0.f); h0[2 * q + 1] = fmaxf(b, 0.f);
            f2unpack(a1[q], a, b);
            h1[2 * q] = fmaxf(a, 0.f); h1[2 * q + 1] = fmaxf(b, 0.f);
        }
        u64 m0[4], m1[4];
        dense2_2r(h0, h1, sw->en_w2, sw->en_b2, h, m0, m1);
#pragma unroll
        for (int p = 0; p < 4; p++) {
            float a, b; f2unpack(m0[p], a, b);
            a = fmaxf(a, 0.f); b = fmaxf(b, 0.f);
            self0[2 * p] = a; self0[2 * p + 1] = b; sp0[p] = f2pack(a, b);
            f2unpack(m1[p], a, b);
            a = fmaxf(a, 0.f); b = fmaxf(b, 0.f);
            self1[2 * p] = a; self1[2 * p + 1] = b; sp1[p] = f2pack(a, b);
        }
    }

    float other0[8], other1[8], food0[8], food1[8];

    // ======== other-agent attention ========
    {
        float mm0 = -__int_as_float(0x7f800000), mm1 = mm0;
        float l0 = 0.f, l1 = 0.f;
        u64 at0[4] = {0,0,0,0}, at1[4] = {0,0,0,0};

#pragma unroll 1
        for (int i = 0; i < 15; i++) {
            float i50[5], i51[5];
            i50[0] = x0[4 + 2 * i];  i51[0] = x1[4 + 2 * i];
            i50[1] = x0[5 + 2 * i];  i51[1] = x1[5 + 2 * i];
            i50[2] = x0[34 + 2 * i]; i51[2] = x1[34 + 2 * i];
            i50[3] = x0[35 + 2 * i]; i51[3] = x1[35 + 2 * i];
            i50[4] = x0[64 + i];     i51[4] = x1[64 + i];

            u64 a0[8], a1[8];
            dense1_2r<5>(i50, i51, sw->oa_w1, sw->oa_b1, hofs, a0, a1);
            float h0[16], h1[16];
#pragma unroll
            for (int q = 0; q < 8; q++) {
                float a, b; f2unpack(a0[q], a, b);
                h0[2 * q] = fmaxf(a, 0.f); h0[2 * q + 1] = fmaxf(b, 0.f);
                f2unpack(a1[q], a, b);
                h1[2 * q] = fmaxf(a, 0.f); h1[2 * q + 1] = fmaxf(b, 0.f);
            }
            u64 e0[4], e1[4];
            dense2_2r(h0, h1, sw->oa_w2, sw->oa_b2, h, e0, e1);
#pragma unroll
            for (int p = 0; p < 4; p++) {
                float a, b;
                f2unpack(e0[p], a, b);
                e0[p] = f2pack(fmaxf(a, 0.f), fmaxf(b, 0.f));
                f2unpack(e1[p], a, b);
                e1[p] = f2pack(fmaxf(a, 0.f), fmaxf(b, 0.f));
            }

            u64 d0 = f2mul(sp0[0], e0[0]);
            u64 d1 = f2mul(sp1[0], e1[0]);
#pragma unroll
            for (int p = 1; p < 4; p++) {
                d0 = f2fma(sp0[p], e0[p], d0);
                d1 = f2fma(sp1[p], e1[p], d1);
            }
            float al, ah, s0, s1;
            f2unpack(d0, al, ah); s0 = al + ah;
            f2unpack(d1, al, ah); s1 = al + ah;
            s0 = (s0 + shflf(s0)) * 0.25f;
            s1 = (s1 + shflf(s1)) * 0.25f;

            float nm0 = fmaxf(mm0, s0), nm1 = fmaxf(mm1, s1);
            float c0 = __expf(mm0 - nm0), c1 = __expf(mm1 - nm1);
            float p0 = __expf(s0 - nm0),  p1 = __expf(s1 - nm1);
            mm0 = nm0; mm1 = nm1;
            l0 = l0 * c0 + p0; l1 = l1 * c1 + p1;
            u64 cc0 = f2splat(c0), pp0 = f2splat(p0);
            u64 cc1 = f2splat(c1), pp1 = f2splat(p1);
#pragma unroll
            for (int p = 0; p < 4; p++) {
                at0[p] = f2fma(cc0, at0[p], f2mul(pp0, e0[p]));
                at1[p] = f2fma(cc1, at1[p], f2mul(pp1, e1[p]));
            }
        }

        float iv0 = __fdividef(1.f, l0), iv1 = __fdividef(1.f, l1);
        float a80[8], a81[8];
#pragma unroll
        for (int p = 0; p < 4; p++) {
            float a, b;
            f2unpack(at0[p], a, b);
            a80[2 * p] = a * iv0; a80[2 * p + 1] = b * iv0;
            f2unpack(at1[p], a, b);
            a81[2 * p] = a * iv1; a81[2 * p + 1] = b * iv1;
        }
        float s0 = 0.f, s1 = 0.f;
#pragma unroll
        for (int d = 0; d < 8; d++) { s0 += a80[d]; s1 += a81[d]; }
        float mu0 = (s0 + shflf(s0)) * (1.f / 16.f);
        float mu1 = (s1 + shflf(s1)) * (1.f / 16.f);
        float v0 = 0.f, v1 = 0.f;
#pragma unroll
        for (int d = 0; d < 8; d++) {
            float c = a80[d] - mu0; v0 += c * c;
            c = a81[d] - mu1; v1 += c * c;
        }
        float rs0 = rsqrtf((v0 + shflf(v0)) * (1.f / 16.f) + 1e-5f);
        float rs1 = rsqrtf((v1 + shflf(v1)) * (1.f / 16.f) + 1e-5f);
#pragma unroll
        for (int d = 0; d < 8; d++) {
            int gd = h * 8 + d;
            float g = sw->oa_g[gd], bb = sw->oa_bln[gd];
            other0[d] = fmaxf((a80[d] - mu0) * rs0 * g + bb, 0.f);
            other1[d] = fmaxf((a81[d] - mu1) * rs1 * g + bb, 0.f);
        }
    }

    // ======== food attention ========
    {
        float mm0 = -__int_as_float(0x7f800000), mm1 = mm0;
        float l0 = 0.f, l1 = 0.f;
        u64 at0[4] = {0,0,0,0}, at1[4] = {0,0,0,0};

#pragma unroll 1
        for (int i = 0; i < 16; i++) {
            float i30[3], i31[3];
            i30[0] = x0[79 + 3 * i]; i31[0] = x1[79 + 3 * i];
            i30[1] = x0[80 + 3 * i]; i31[1] = x1[80 + 3 * i];
            i30[2] = x0[81 + 3 * i]; i31[2] = x1[81 + 3 * i];

            u64 a0[8], a1[8];
            dense1_2r<3>(i30, i31, sw->g_w1, sw->g_b1, hofs, a0, a1);
            float h0[16], h1[16];
#pragma unroll
            for (int q = 0; q < 8; q++) {
                float a, b; f2unpack(a0[q], a, b);
                h0[2 * q] = fmaxf(a, 0.f); h0[2 * q + 1] = fmaxf(b, 0.f);
                f2unpack(a1[q], a, b);
                h1[2 * q] = fmaxf(a, 0.f); h1[2 * q + 1] = fmaxf(b, 0.f);
            }
            u64 e0[4], e1[4];
            dense2_2r(h0, h1, sw->g_w2, sw->g_b2, h, e0, e1);
#pragma unroll
            for (int p = 0; p < 4; p++) {
                float a, b;
                f2unpack(e0[p], a, b);
                e0[p] = f2pack(fmaxf(a, 0.f), fmaxf(b, 0.f));
                f2unpack(e1[p], a, b);
                e1[p] = f2pack(fmaxf(a, 0.f), fmaxf(b, 0.f));
            }

            u64 d0 = f2mul(sp0[0], e0[0]);
            u64 d1 = f2mul(sp1[0], e1[0]);
#pragma unroll
            for (int p = 1; p < 4; p++) {
                d0 = f2fma(sp0[p], e0[p], d0);
                d1 = f2fma(sp1[p], e1[p], d1);
            }
            float al, ah, s0, s1;
            f2unpack(d0, al, ah); s0 = al + ah;
            f2unpack(d1, al, ah); s1 = al + ah;
            s0 = (s0 + shflf(s0)) * 0.25f;
            s1 = (s1 + shflf(s1)) * 0.25f;

            float nm0 = fmaxf(mm0, s0), nm1 = fmaxf(mm1, s1);
            float c0 = __expf(mm0 - nm0), c1 = __expf(mm1 - nm1);
            float p0 = __expf(s0 - nm0),  p1 = __expf(s1 - nm1);
            mm0 = nm0; mm1 = nm1;
            l0 = l0 * c0 + p0; l1 = l1 * c1 + p1;
            u64 cc0 = f2splat(c0), pp0 = f2splat(p0);
            u64 cc1 = f2splat(c1), pp1 = f2splat(p1);
#pragma unroll
            for (int p = 0; p < 4; p++) {
                at0[p] = f2fma(cc0, at0[p], f2mul(pp0, e0[p]));
                at1[p] = f2fma(cc1, at1[p], f2mul(pp1, e1[p]));
            }
        }

        float iv0 = __fdividef(1.f, l0), iv1 = __fdividef(1.f, l1);
        float a80[8], a81[8];
#pragma unroll
        for (int p = 0; p < 4; p++) {
            float a, b;
            f2unpack(at0[p], a, b);
            a80[2 * p] = a * iv0; a80[2 * p + 1] = b * iv0;
            f2unpack(at1[p], a, b);
            a81[2 * p] = a * iv1; a81[2 * p + 1] = b * iv1;
        }
        float s0 = 0.f, s1 = 0.f;
#pragma unroll
        for (int d = 0; d < 8; d++) { s0 += a80[d]; s1 += a81[d]; }
        float mu0 = (s0 + shflf(s0)) * (1.f / 16.f);
        float mu1 = (s1 + shflf(s1)) * (1.f / 16.f);
        float v0 = 0.f, v1 = 0.f;
#pragma unroll
        for (int d = 0; d < 8; d++) {
            float c = a80[d] - mu0; v0 += c * c;
            c = a81[d] - mu1; v1 += c * c;
        }
        float rs0 = rsqrtf((v0 + shflf(v0)) * (1.f / 16.f) + 1e-5f);
        float rs1 = rsqrtf((v1 + shflf(v1)) * (1.f / 16.f) + 1e-5f);
#pragma unroll
        for (int d = 0; d < 8; d++) {
            int gd = h * 8 + d;
            float g = sw->g_g[gd], bb = sw->g_bln[gd];
            food0[d] = fmaxf((a80[d] - mu0) * rs0 * g + bb, 0.f);
            food1[d] = fmaxf((a81[d] - mu1) * rs1 * g + bb, 0.f);
        }
    }

    // ---------------- merge head ----------------
    float h1l0[16], h1l1[16];
    {
        u64 m0[8], m1[8], t0[8], t1[8];
        const ulonglong2* bp = reinterpret_cast<const ulonglong2*>(sw->m_b1 + h * 16);
#pragma unroll
        for (int q = 0; q < 4; q++) {
            ulonglong2 t = bp[q];
            m0[2 * q] = t.x; m0[2 * q + 1] = t.y;
            m1[2 * q] = t.x; m1[2 * q + 1] = t.y;
            t0[2 * q] = 0ull; t0[2 * q + 1] = 0ull;
            t1[2 * q] = 0ull; t1[2 * q + 1] = 0ull;
        }
        dense32_2r(self0,  self1,  sw->m_w1, h * 8,      h, m0, m1, t0, t1);
        dense32_2r(food0,  food1,  sw->m_w1, 16 + h * 8, h, m0, m1, t0, t1);
        dense32_2r(other0, other1, sw->m_w1, 32 + h * 8, h, m0, m1, t0, t1);
#pragma unroll
        for (int p = 0; p < 8; p++) {
            m0[p] = f2add(m0[p], shfl64(t0[p]));
            m1[p] = f2add(m1[p], shfl64(t1[p]));
        }
#pragma unroll
        for (int p = 0; p < 8; p++) {
            float a, b;
            f2unpack(m0[p], a, b);
            h1l0[2 * p] = fmaxf(a, 0.01f * a); h1l0[2 * p + 1] = fmaxf(b, 0.01f * b);
            f2unpack(m1[p], a, b);
            h1l1[2 * p] = fmaxf(a, 0.01f * a); h1l1[2 * p + 1] = fmaxf(b, 0.01f * b);
        }
    }

    float h2l0[16], h2l1[16];
    {
        u64 m0[8], m1[8], t0[8], t1[8];
        const ulonglong2* bp = reinterpret_cast<const ulonglong2*>(sw->m_b2 + h * 16);
#pragma unroll
        for (int q = 0; q < 4; q++) {
            ulonglong2 t = bp[q];
            m0[2 * q] = t.x; m0[2 * q + 1] = t.y;
            m1[2 * q] = t.x; m1[2 * q + 1] = t.y;
            t0[2 * q] = 0ull; t0[2 * q + 1] = 0ull;
            t1[2 * q] = 0ull; t1[2 * q + 1] = 0ull;
        }
        dense32_2r(h1l0,     h1l1,     sw->m_w2, 16 * h,     h, m0, m1, t0, t1);
        dense32_2r(h1l0 + 8, h1l1 + 8, sw->m_w2, 16 * h + 8, h, m0, m1, t0, t1);
#pragma unroll
        for (int p = 0; p < 8; p++) {
            m0[p] = f2add(m0[p], shfl64(t0[p]));
            m1[p] = f2add(m1[p], shfl64(t1[p]));
        }
#pragma unroll
        for (int p = 0; p < 8; p++) {
            float a, b;
            f2unpack(m0[p], a, b);
            h2l0[2 * p] = fmaxf(a, 0.01f * a); h2l0[2 * p + 1] = fmaxf(b, 0.01f * b);
            f2unpack(m1[p], a, b);
            h2l1[2 * p] = fmaxf(a, 0.01f * a); h2l1[2 * p + 1] = fmaxf(b, 0.01f * b);
        }
    }

    {
        u64 acc0, acc1;
        if (h == 0) {
            u64 bias = *reinterpret_cast<const u64*>(sw->m_b3);
            acc0 = bias; acc1 = bias;
        } else {
            acc0 = 0ull; acc1 = 0ull;
        }
        const u64* w3 = reinterpret_cast<const u64*>(sw->m_w3);
#pragma unroll
        for (int j = 0; j < 16; j++) {
            const int k = h * 16 + j;
            u64 wv = w3[k];
            acc0 = f2fma(f2splat(h2l0[j]), wv, acc0);
            acc1 = f2fma(f2splat(h2l1[j]), wv, acc1);
        }
        acc0 = f2add(acc0, shfl64(acc0));
        acc1 = f2add(acc1, shfl64(acc1));
        if (h == 0) {
            float o0, o1, o2, o3;
            f2unpack(acc0, o0, o1);
            f2unpack(acc1, o2, o3);
            float4 o = make_float4(tanhf(o0), tanhf(o1), tanhf(o2), tanhf(o3));
            reinterpret_cast<float4*>(out)[blockIdx.x * (ROWS / 2) + pr] = o;
        }
    }
}

extern "C" void kernel_launch(void* const* d_in, const int* in_sizes, int n_in,
                              void* d_out, int out_size) {
    const float* s_in = (const float*)d_in[0];
    const int B = in_sizes[0] / OBS;
    const size_t shbytes = (size_t)ROWS * OBS * sizeof(float) + sizeof(SW);
    cudaFuncSetAttribute(actor_kernel,
                         cudaFuncAttributeMaxDynamicSharedMemorySize, (int)shbytes);
    dim3 grid((B + ROWS - 1) / ROWS), block(NT);
    actor_kernel<<<grid, block, shbytes>>>(
        s_in,
        (const float*)d_in[1],  (const float*)d_in[2],
        (const float*)d_in[3],  (const float*)d_in[4],
        (const float*)d_in[5],  (const float*)d_in[6],
        (const float*)d_in[7],  (const float*)d_in[8],
        (const float*)d_in[9],  (const float*)d_in[10],
        (const float*)d_in[11], (const float*)d_in[12],
        (const float*)d_in[13], (const float*)d_in[14],
        (const float*)d_in[15], (const float*)d_in[16],
        (const float*)d_in[17], (const float*)d_in[18],
        (const float*)d_in[19], (const float*)d_in[20],
        (const float*)d_in[21], (const float*)d_in[22],
        (float*)d_out, B);
}